// round 17
// baseline (speedup 1.0000x reference)
#include <cuda_runtime.h>
#include <cuda_bf16.h>
#include <cstdint>

#define NN 50000
#define EE 800000
#define DD 128
#define OUTD 64
#define NG 64
#define NB 196            // scan blocks (196*256 >= NN)

// Scratch (device globals; no allocation allowed)
__device__ float g_agg[NN * DD];
__device__ float g_bufA[NN * DD];
__device__ float g_bufB[NN * DD];
__device__ float g_pool[NG * DD];
__device__ float g_cnt[NG];
__device__ int   g_deg[NN];
__device__ int   g_rowptr[NN + 1];
__device__ int   g_csr[EE];
__device__ int   g_blksum[NB];
__device__ int   g_blkoff[NB];
// Pre-split weights: 6 matrices [W1l, W1r, W2l, W2r, W3l, W3r], each 128x128 bf16
__device__ uint16_t g_wH[6 * 128 * 128];
__device__ uint16_t g_wL[6 * 128 * 128];

// ===========================================================================
// helpers
// ===========================================================================
__device__ __forceinline__ void mma_bf16(float* c, const uint32_t* a,
                                         uint32_t b0, uint32_t b1) {
    asm volatile(
        "mma.sync.aligned.m16n8k16.row.col.f32.bf16.bf16.f32 "
        "{%0,%1,%2,%3}, {%4,%5,%6,%7}, {%8,%9}, {%0,%1,%2,%3};"
        : "+f"(c[0]), "+f"(c[1]), "+f"(c[2]), "+f"(c[3])
        : "r"(a[0]), "r"(a[1]), "r"(a[2]), "r"(a[3]), "r"(b0), "r"(b1));
}

__device__ __forceinline__ void split2(float x, float y, uint32_t& hi, uint32_t& lo) {
    __nv_bfloat16 hx = __float2bfloat16(x);
    __nv_bfloat16 hy = __float2bfloat16(y);
    __nv_bfloat16 lx = __float2bfloat16(x - __bfloat162float(hx));
    __nv_bfloat16 ly = __float2bfloat16(y - __bfloat162float(hy));
    hi = ((uint32_t)__bfloat16_as_ushort(hy) << 16) | __bfloat16_as_ushort(hx);
    lo = ((uint32_t)__bfloat16_as_ushort(ly) << 16) | __bfloat16_as_ushort(lx);
}

// ===========================================================================
// W pre-split: 6 fp32 128x128 matrices -> bf16 hi/lo planes (runs once)
// ===========================================================================
__global__ void wsplit_kernel(const float* __restrict__ W0, const float* __restrict__ W1,
                              const float* __restrict__ W2, const float* __restrict__ W3,
                              const float* __restrict__ W4, const float* __restrict__ W5) {
    int t = blockIdx.x * blockDim.x + threadIdx.x;   // t < 6*4096
    if (t >= 6 * 4096) return;
    int m = t >> 12;
    int off = (t & 4095) << 2;
    const float* src = (m == 0) ? W0 : (m == 1) ? W1 : (m == 2) ? W2
                      : (m == 3) ? W3 : (m == 4) ? W4 : W5;
    float4 v = *reinterpret_cast<const float4*>(src + off);
    uint2 hv, lv;
    split2(v.x, v.y, hv.x, lv.x);
    split2(v.z, v.w, hv.y, lv.y);
    size_t p = (size_t)m * 16384 + off;
    *reinterpret_cast<uint2*>(g_wH + p) = hv;
    *reinterpret_cast<uint2*>(g_wL + p) = lv;
}

// ===========================================================================
// CSR build (hierarchical scan)
// ===========================================================================
__global__ void zero_deg_kernel() {
    int t = blockIdx.x * blockDim.x + threadIdx.x;
    if (t < NN) g_deg[t] = 0;
}
__global__ void count_deg_kernel(const int* __restrict__ ei) {
    int e = blockIdx.x * blockDim.x + threadIdx.x;
    if (e < EE) atomicAdd(&g_deg[ei[EE + e]], 1);
}
__global__ void scan_blksum_kernel() {
    int t = blockIdx.x * blockDim.x + threadIdx.x;
    int v = (t < NN) ? g_deg[t] : 0;
#pragma unroll
    for (int off = 16; off > 0; off >>= 1)
        v += __shfl_down_sync(0xFFFFFFFF, v, off);
    __shared__ int ws[8];
    if ((threadIdx.x & 31) == 0) ws[threadIdx.x >> 5] = v;
    __syncthreads();
    if (threadIdx.x == 0) {
        int s = 0;
#pragma unroll
        for (int i = 0; i < 8; i++) s += ws[i];
        g_blksum[blockIdx.x] = s;
    }
}
__global__ void scan_offsets_kernel() {
    int t = threadIdx.x;   // 256 >= NB
    int v = (t < NB) ? g_blksum[t] : 0;
    __shared__ int s[256];
    s[t] = v;
    __syncthreads();
    for (int off = 1; off < 256; off <<= 1) {
        int u = (t >= off) ? s[t - off] : 0;
        __syncthreads();
        s[t] += u;
        __syncthreads();
    }
    if (t < NB) g_blkoff[t] = s[t] - v;   // exclusive
    if (t == 255) g_rowptr[NN] = s[255];
}
__global__ void scan_final_kernel() {
    int t = blockIdx.x * blockDim.x + threadIdx.x;
    int v = (t < NN) ? g_deg[t] : 0;
    __shared__ int s[256];
    s[threadIdx.x] = v;
    __syncthreads();
    for (int off = 1; off < 256; off <<= 1) {
        int u = (threadIdx.x >= off) ? s[threadIdx.x - off] : 0;
        __syncthreads();
        s[threadIdx.x] += u;
        __syncthreads();
    }
    if (t < NN) {
        g_rowptr[t] = g_blkoff[blockIdx.x] + s[threadIdx.x] - v;
        g_deg[t] = 0;   // reset cursor for fill
    }
}
__global__ void fill_csr_kernel(const int* __restrict__ ei) {
    int e = blockIdx.x * blockDim.x + threadIdx.x;
    if (e >= EE) return;
    int d = ei[EE + e];
    int slot = atomicAdd(&g_deg[d], 1);
    g_csr[g_rowptr[d] + slot] = ei[e];
}

// ===========================================================================
// Gather-aggregate (CSR): warp per dst node, lane owns one float4; unroll 4
// ===========================================================================
__global__ void gather_kernel(const float* __restrict__ in,
                              float* __restrict__ agg) {
    int w = (blockIdx.x * blockDim.x + threadIdx.x) >> 5;
    int lane = threadIdx.x & 31;
    if (w >= NN) return;
    int beg = g_rowptr[w];
    int end = g_rowptr[w + 1];
    float4 a0 = make_float4(0.f, 0.f, 0.f, 0.f);
    float4 a1 = make_float4(0.f, 0.f, 0.f, 0.f);
    float4 a2 = make_float4(0.f, 0.f, 0.f, 0.f);
    float4 a3 = make_float4(0.f, 0.f, 0.f, 0.f);
    int i = beg;
    for (; i + 3 < end; i += 4) {
        int s0 = g_csr[i], s1 = g_csr[i + 1], s2 = g_csr[i + 2], s3 = g_csr[i + 3];
        float4 v0 = reinterpret_cast<const float4*>(in + (size_t)s0 * DD)[lane];
        float4 v1 = reinterpret_cast<const float4*>(in + (size_t)s1 * DD)[lane];
        float4 v2 = reinterpret_cast<const float4*>(in + (size_t)s2 * DD)[lane];
        float4 v3 = reinterpret_cast<const float4*>(in + (size_t)s3 * DD)[lane];
        a0.x += v0.x; a0.y += v0.y; a0.z += v0.z; a0.w += v0.w;
        a1.x += v1.x; a1.y += v1.y; a1.z += v1.z; a1.w += v1.w;
        a2.x += v2.x; a2.y += v2.y; a2.z += v2.z; a2.w += v2.w;
        a3.x += v3.x; a3.y += v3.y; a3.z += v3.z; a3.w += v3.w;
    }
    for (; i < end; i++) {
        int s0 = g_csr[i];
        float4 v0 = reinterpret_cast<const float4*>(in + (size_t)s0 * DD)[lane];
        a0.x += v0.x; a0.y += v0.y; a0.z += v0.z; a0.w += v0.w;
    }
    a0.x += a1.x + a2.x + a3.x;
    a0.y += a1.y + a2.y + a3.y;
    a0.z += a1.z + a2.z + a3.z;
    a0.w += a1.w + a2.w + a3.w;
    reinterpret_cast<float4*>(agg + (size_t)w * DD)[lane] = a0;
}

// ===========================================================================
// Split-bf16 mma.sync SAGE GEMM v4:
//   A tiles (hi/lo) in smem (70.5KB -> occupancy 2);
//   W fragments loaded directly from pre-split global bf16 planes (L1-hot).
//   out[128-row tile] = maybe_relu(agg @ Wl^T + b + X @ Wr^T)
//   D += Ah@Wh + Ah@Wl + Al@Wh  (rel err ~1e-5)
// ===========================================================================
#define SP_B 272                     // smem row stride bytes (conflict-free)
#define TILE_B (128 * SP_B)          // 34816
#define SM_BIAS 0
#define SM_AH   1024
#define SM_AL   (SM_AH + TILE_B)
#define SM_TOTAL (SM_AL + TILE_B)    // 70656 bytes -> 2 blocks/SM

// Convert a 128x128 fp32 tile into hi/lo bf16 smem tiles (row-major, SP_B).
__device__ __forceinline__ void convert_tile(const float* __restrict__ src,
                                             int row0,
                                             char* dstH, char* dstL, int tid) {
    for (int idx = tid; idx < 128 * 32; idx += 256) {
        int r = idx >> 5;
        int k4 = (idx & 31) << 2;
        float4 v;
        if (row0 + r < NN)
            v = *reinterpret_cast<const float4*>(src + (size_t)(row0 + r) * DD + k4);
        else
            v = make_float4(0.f, 0.f, 0.f, 0.f);
        uint2 hv, lv;
        split2(v.x, v.y, hv.x, lv.x);
        split2(v.z, v.w, hv.y, lv.y);
        uint32_t off = (uint32_t)(r * SP_B + k4 * 2);
        *reinterpret_cast<uint2*>(dstH + off) = hv;
        *reinterpret_cast<uint2*>(dstL + off) = lv;
    }
}

__global__ __launch_bounds__(256, 2)
void sage_gemm_mma4_kernel(const float* __restrict__ A,
                           const float* __restrict__ X,
                           const uint16_t* __restrict__ WlH,
                           const uint16_t* __restrict__ WlL,
                           const uint16_t* __restrict__ WrH,
                           const uint16_t* __restrict__ WrL,
                           const float* __restrict__ bias,
                           float* __restrict__ out,
                           int relu) {
    extern __shared__ char smem[];
    char* sAH = smem + SM_AH;
    char* sAL = smem + SM_AL;
    float* bs = (float*)(smem + SM_BIAS);

    int tid = threadIdx.x;
    int wid = tid >> 5;
    int lane = tid & 31;
    int wr = wid & 3;    // row group: rows wr*32 .. +32
    int wc = wid >> 2;   // col group: cols wc*64 .. +64
    int gr = lane >> 2;          // 0..7
    int ko = (lane & 3) << 2;    // k byte offset (bf16 pair index *4)

    int row0 = blockIdx.x * 128;
    if (tid < 128) bs[tid] = bias[tid];

    float acc[2][8][4];
#pragma unroll
    for (int mf = 0; mf < 2; mf++)
#pragma unroll
        for (int nf = 0; nf < 8; nf++)
#pragma unroll
            for (int q = 0; q < 4; q++) acc[mf][nf][q] = 0.f;

    for (int phase = 0; phase < 2; phase++) {
        const float* In = phase ? X : A;
        const char* WH = (const char*)(phase ? WrH : WlH);
        const char* WL = (const char*)(phase ? WrL : WlL);
        if (phase) __syncthreads();  // phase-0 MMAs done before overwrite
        convert_tile(In, row0, sAH, sAL, tid);
        __syncthreads();

        const char* pa0 = sAH + (wr * 32 + gr) * SP_B + ko;
        const char* pl0 = sAL + (wr * 32 + gr) * SP_B + ko;
        // W fragment base: row n = wc*64 + nf*8 + gr, 256 B/row, + ks*32 + ko
        const char* pwh = WH + (wc * 64 + gr) * 256 + ko;
        const char* pwl = WL + (wc * 64 + gr) * 256 + ko;

#pragma unroll
        for (int ks = 0; ks < 8; ks++) {
            int kb = ks * 32;
            uint32_t ah[2][4], al[2][4];
#pragma unroll
            for (int mf = 0; mf < 2; mf++) {
                const char* pa = pa0 + mf * 16 * SP_B + kb;
                ah[mf][0] = *(const uint32_t*)(pa);
                ah[mf][1] = *(const uint32_t*)(pa + 8 * SP_B);
                ah[mf][2] = *(const uint32_t*)(pa + 16);
                ah[mf][3] = *(const uint32_t*)(pa + 8 * SP_B + 16);
                const char* pl = pl0 + mf * 16 * SP_B + kb;
                al[mf][0] = *(const uint32_t*)(pl);
                al[mf][1] = *(const uint32_t*)(pl + 8 * SP_B);
                al[mf][2] = *(const uint32_t*)(pl + 16);
                al[mf][3] = *(const uint32_t*)(pl + 8 * SP_B + 16);
            }
#pragma unroll
            for (int nf = 0; nf < 8; nf++) {
                const char* ph = pwh + nf * 8 * 256 + kb;
                uint32_t bh0 = *(const uint32_t*)(ph);
                uint32_t bh1 = *(const uint32_t*)(ph + 16);
                const char* pw = pwl + nf * 8 * 256 + kb;
                uint32_t bl0 = *(const uint32_t*)(pw);
                uint32_t bl1 = *(const uint32_t*)(pw + 16);
                mma_bf16(acc[0][nf], ah[0], bh0, bh1);
                mma_bf16(acc[1][nf], ah[1], bh0, bh1);
                mma_bf16(acc[0][nf], al[0], bh0, bh1);
                mma_bf16(acc[1][nf], al[1], bh0, bh1);
                mma_bf16(acc[0][nf], ah[0], bl0, bl1);
                mma_bf16(acc[1][nf], ah[1], bl0, bl1);
            }
        }
    }

    // Epilogue: rows (gr, gr+8) per 16-row mfrag; cols 2*(lane&3)+{0,1} per nfrag
    int crow0 = row0 + wr * 32;
    int ccol0 = wc * 64 + ((lane & 3) << 1);
#pragma unroll
    for (int mf = 0; mf < 2; mf++) {
#pragma unroll
        for (int half = 0; half < 2; half++) {
            int row = crow0 + mf * 16 + gr + half * 8;
            if (row >= NN) continue;
#pragma unroll
            for (int nf = 0; nf < 8; nf++) {
                int col = ccol0 + nf * 8;
                float v0 = acc[mf][nf][half * 2 + 0] + bs[col];
                float v1 = acc[mf][nf][half * 2 + 1] + bs[col + 1];
                if (relu) { v0 = fmaxf(v0, 0.f); v1 = fmaxf(v1, 0.f); }
                *reinterpret_cast<float2*>(out + (size_t)row * DD + col) =
                    make_float2(v0, v1);
            }
        }
    }
}

// ===========================================================================
// Pool + final linear
// ===========================================================================
__global__ void zero_pool_kernel() {
    int t = blockIdx.x * blockDim.x + threadIdx.x;
    if (t < NG * DD) g_pool[t] = 0.f;
    if (t < NG) g_cnt[t] = 0.f;
}
__global__ void pool_kernel(const float* __restrict__ h,
                            const int* __restrict__ batch) {
    int t = blockIdx.x * blockDim.x + threadIdx.x;
    int n = t >> 5;
    int lane = t & 31;
    if (n >= NN) return;
    int g = batch[n];
    float4 v = reinterpret_cast<const float4*>(h + (size_t)n * DD)[lane];
    float* dp = g_pool + (size_t)g * DD + lane * 4;
    asm volatile("red.global.add.v4.f32 [%0], {%1,%2,%3,%4};"
                 :: "l"(dp), "f"(v.x), "f"(v.y), "f"(v.z), "f"(v.w) : "memory");
    if (lane == 0) atomicAdd(&g_cnt[g], 1.0f);
}
__global__ void final_kernel(const float* __restrict__ Wlin,
                             const float* __restrict__ blin,
                             float* __restrict__ out) {
    int g = blockIdx.x;
    int o = threadIdx.x;
    __shared__ float ps[DD];
    ps[o] = g_pool[g * DD + o];
    ps[o + 64] = g_pool[g * DD + o + 64];
    __syncthreads();
    float inv = 1.f / fmaxf(g_cnt[g], 1.f);
    float dot = 0.f;
#pragma unroll 4
    for (int k = 0; k < DD; k++) dot += ps[k] * Wlin[o * DD + k];
    out[g * OUTD + o] = dot * inv + blin[o];
}

// ===========================================================================
extern "C" void kernel_launch(void* const* d_in, const int* in_sizes, int n_in,
                              void* d_out, int out_size) {
    const float* x    = (const float*)d_in[0];
    const int*   ei   = (const int*)d_in[1];
    const int*   batch= (const int*)d_in[2];
    const float* W1l  = (const float*)d_in[3];
    const float* b1l  = (const float*)d_in[4];
    const float* W1r  = (const float*)d_in[5];
    const float* W2l  = (const float*)d_in[6];
    const float* b2l  = (const float*)d_in[7];
    const float* W2r  = (const float*)d_in[8];
    const float* W3l  = (const float*)d_in[9];
    const float* b3l  = (const float*)d_in[10];
    const float* W3r  = (const float*)d_in[11];
    const float* Wlin = (const float*)d_in[12];
    const float* blin = (const float*)d_in[13];
    float* out = (float*)d_out;

    cudaFuncSetAttribute(sage_gemm_mma4_kernel,
                         cudaFuncAttributeMaxDynamicSharedMemorySize, SM_TOTAL);

    const int edgeBlocks = (EE + 255) / 256;
    const int gatherBlocks = (NN * 32 + 255) / 256;
    const int gemmBlocks = (NN + 127) / 128;
    const int poolBlocks = (NN * 32 + 255) / 256;

    float* devAgg;  cudaGetSymbolAddress((void**)&devAgg, g_agg);
    float* devA;    cudaGetSymbolAddress((void**)&devA, g_bufA);
    float* devB;    cudaGetSymbolAddress((void**)&devB, g_bufB);
    uint16_t* wH;   cudaGetSymbolAddress((void**)&wH, g_wH);
    uint16_t* wL;   cudaGetSymbolAddress((void**)&wL, g_wL);

    // Pre-split all 6 weight matrices into bf16 hi/lo planes (once)
    wsplit_kernel<<<96, 256>>>(W1l, W1r, W2l, W2r, W3l, W3r);

    // Build CSR (dst-grouped) once; hierarchical scan.
    zero_deg_kernel<<<NB, 256>>>();
    count_deg_kernel<<<edgeBlocks, 256>>>(ei);
    scan_blksum_kernel<<<NB, 256>>>();
    scan_offsets_kernel<<<1, 256>>>();
    scan_final_kernel<<<NB, 256>>>();   // writes rowptr, resets g_deg cursors
    fill_csr_kernel<<<edgeBlocks, 256>>>(ei);

    // Layer 1
    gather_kernel<<<gatherBlocks, 256>>>(x, devAgg);
    sage_gemm_mma4_kernel<<<gemmBlocks, 256, SM_TOTAL>>>(
        devAgg, x, wH + 0 * 16384, wL + 0 * 16384, wH + 1 * 16384, wL + 1 * 16384,
        b1l, devA, 1);
    // Layer 2
    gather_kernel<<<gatherBlocks, 256>>>(devA, devAgg);
    sage_gemm_mma4_kernel<<<gemmBlocks, 256, SM_TOTAL>>>(
        devAgg, devA, wH + 2 * 16384, wL + 2 * 16384, wH + 3 * 16384, wL + 3 * 16384,
        b2l, devB, 1);
    // Layer 3
    gather_kernel<<<gatherBlocks, 256>>>(devB, devAgg);
    sage_gemm_mma4_kernel<<<gemmBlocks, 256, SM_TOTAL>>>(
        devAgg, devB, wH + 4 * 16384, wL + 4 * 16384, wH + 5 * 16384, wL + 5 * 16384,
        b3l, devA, 0);
    // Pool + final linear
    zero_pool_kernel<<<(NG * DD + 255) / 256, 256>>>();
    pool_kernel<<<poolBlocks, 256>>>(devA, batch);
    final_kernel<<<NG, OUTD>>>(Wlin, blin, out);
}